// round 14
// baseline (speedup 1.0000x reference)
#include <cuda_runtime.h>
#include <cuda_bf16.h>
#include <math.h>
#include <stdint.h>

// Problem constants
#define BATCH 8
#define NPTS  2048
#define CDIM  128
#define PDIM  3
#define ODIM  256
#define KNN   16
#define ROWS  (BATCH * NPTS)       // 16384
#define KPAD  144                  // 131 padded up to multiple of 16
#define BN_EPS 1e-5f
#define INVN  (1.0f / (float)ROWS)
#define MBLK  (ROWS / 128)         // 128 m-blocks in gemm grid

typedef unsigned long long u64;

// ---------------- scratch (static device memory; no allocations) -------------
__device__ int   g_nn[ROWS * KNN];                 // 1 MB
__device__ float g_avg[ROWS * KPAD];               // 9.4 MB (tf32-pre-rounded)
__device__ float g_w1h[KPAD * ODIM];               // padded W1, tf32 hi
__device__ float g_w1l[KPAD * ODIM];               // padded W1, tf32 lo
__device__ float g_w2h[ODIM * ODIM];               // W2 hi
__device__ float g_w2l[ODIM * ODIM];               // W2 lo
__device__ float g_c1[ROWS * ODIM];                // 16.8 MB (pre-BN layer1)
__device__ float g_partM[2][MBLK][2 * ODIM];       // gemm-epilogue partial sum|sumsq
__device__ float g_scale[2][ODIM];                 // BN scale per layer
__device__ float g_shift[2][ODIM];                 // BN shift per layer

// ---------------- tf32 helpers ------------------------------------------------
__device__ __forceinline__ uint32_t f2tf32(float x) {
    uint32_t r;
    asm("cvt.rna.tf32.f32 %0, %1;" : "=r"(r) : "f"(x));
    return r;
}
__device__ __forceinline__ void tf32_split(float x, float& hi, float& lo) {
    uint32_t h = f2tf32(x);
    hi = __uint_as_float(h);
    lo = __uint_as_float(f2tf32(x - hi));
}

// ---------------- prep: pad + pre-split W1, pre-split W2 ----------------------
__global__ void prep1_kernel(const float* __restrict__ W1) {
    int k = blockIdx.x;          // 0..143
    int o = threadIdx.x;         // 0..255
    float v = (k < 131) ? W1[k * ODIM + o] : 0.0f;
    float h, l;
    tf32_split(v, h, l);
    g_w1h[k * ODIM + o] = h;
    g_w1l[k * ODIM + o] = l;
}
__global__ void prep2_kernel(const float* __restrict__ W2) {
    int k = blockIdx.x;          // 0..255
    int o = threadIdx.x;         // 0..255
    float h, l;
    tf32_split(W2[k * ODIM + o], h, l);
    g_w2h[k * ODIM + o] = h;
    g_w2l[k * ODIM + o] = l;
}

// ---------------- KNN --------------------------------------------------------
// 2 threads per query (even/odd point parity); register top-16 via deferred
// batched inserts; unique u64 keys (dist_bits<<32 | idx) = exact top_k
// semantics. Hot-loop gate is the FLOAT compare d <= wf (superset of
// key < wmax); the flush re-gates with the exact u64 compare, so the final
// selected set is bit-identical. wf refreshed only after flushes.
__device__ __forceinline__ u64 umax64(u64 a, u64 b) { return a > b ? a : b; }

__device__ __forceinline__ u64 max16(const u64 (&bk)[KNN]) {
    u64 m0 = umax64(bk[0], bk[1]),   m1 = umax64(bk[2], bk[3]);
    u64 m2 = umax64(bk[4], bk[5]),   m3 = umax64(bk[6], bk[7]);
    u64 m4 = umax64(bk[8], bk[9]),   m5 = umax64(bk[10], bk[11]);
    u64 m6 = umax64(bk[12], bk[13]), m7 = umax64(bk[14], bk[15]);
    m0 = umax64(m0, m1); m2 = umax64(m2, m3);
    m4 = umax64(m4, m5); m6 = umax64(m6, m7);
    m0 = umax64(m0, m2); m4 = umax64(m4, m6);
    return umax64(m0, m4);
}

__device__ __forceinline__ void insert16(u64 (&bk)[KNN], u64& wmax, u64 key) {
#pragma unroll
    for (int k = 0; k < KNN; k++) {
        if (bk[k] == wmax) bk[k] = key;      // unique keys: exactly one slot
    }
    wmax = max16(bk);
}

__global__ void __launch_bounds__(64) knn_kernel(const float* __restrict__ pos) {
    __shared__ float4 sp[NPTS];                    // 32 KB
    __shared__ u64 sbuf[16][64];                   // 8 KB, [slot][lane]
    int tid = threadIdx.x;
    int bb = blockIdx.x >> 6;                      // batch (64 blocks per batch)
    int r0 = (blockIdx.x & 63) << 5;               // query offset (32 queries/block)
    const float* pb = pos + bb * NPTS * PDIM;
    for (int j = tid; j < NPTS; j += 64) {
        sp[j] = make_float4(pb[j * 3 + 0], pb[j * 3 + 1], pb[j * 3 + 2], 0.0f);
    }
    __syncthreads();

    int qi = r0 + (tid >> 1);                      // query index (pairs share)
    int sub = tid & 1;                             // parity of points scanned
    float4 q = sp[qi];

    // seed: thread's first 16 candidates (points 0..31) are the initial top-16
    u64 bk[KNN];
#pragma unroll
    for (int k = 0; k < KNN; k++) {
        int j = 2 * k + sub;
        float4 p = sp[j];
        float dx = q.x - p.x, dy = q.y - p.y, dz = q.z - p.z;
        float d = dx * dx + dy * dy + dz * dz;
        bk[k] = ((u64)__float_as_uint(d) << 32) | (unsigned)j;
    }
    u64 wmax = max16(bk);
    float wf = __uint_as_float((unsigned)(wmax >> 32));

    int n = 0;
    for (int j0 = 32; j0 < NPTS; j0 += 16) {
#pragma unroll
        for (int c = 0; c < 8; c++) {
            int j = j0 + 2 * c + sub;
            float4 p = sp[j];
            float dx = q.x - p.x, dy = q.y - p.y, dz = q.z - p.z;
            float d = dx * dx + dy * dy + dz * dz;
            if (d <= wf) {                          // float gate (superset)
                sbuf[n][tid] = ((u64)__float_as_uint(d) << 32) | (unsigned)j;
                n++;
            }
        }
        if (__any_sync(0xFFFFFFFFu, n >= 8)) {
            int mx = __reduce_max_sync(0xFFFFFFFFu, n);
            for (int k = 0; k < mx; k++) {          // lockstep insert rounds
                u64 key = sbuf[k][tid];
                if (k < n && key < wmax) insert16(bk, wmax, key);  // exact gate
            }
            n = 0;
            wf = __uint_as_float((unsigned)(wmax >> 32));
        }
    }
    {   // final flush
        int mx = __reduce_max_sync(0xFFFFFFFFu, n);
        for (int k = 0; k < mx; k++) {
            u64 key = sbuf[k][tid];
            if (k < n && key < wmax) insert16(bk, wmax, key);
        }
    }

    // pair merge: even lane absorbs odd lane's 16 keys (union superset, exact)
#pragma unroll
    for (int k = 0; k < KNN; k++) {
        u64 pk = __shfl_xor_sync(0xFFFFFFFFu, bk[k], 1);
        if (sub == 0 && pk < wmax) insert16(bk, wmax, pk);
    }
    if (sub == 0) {
        int* o = g_nn + (bb * NPTS + qi) * KNN;
#pragma unroll
        for (int k = 0; k < KNN; k++) o[k] = (int)(bk[k] & 0xFFFFFFFFu);
    }
}

// ---------------- gather neighbors + mean -> avg (tf32-pre-rounded) -----------
__global__ void __launch_bounds__(128) gather_avg_kernel(const float* __restrict__ x,
                                                         const float* __restrict__ pos) {
    int row = blockIdx.x;
    int bb = row >> 11;
    __shared__ int sidx[KNN];
    if (threadIdx.x < KNN) sidx[threadIdx.x] = g_nn[row * KNN + threadIdx.x];
    __syncthreads();

    const float* xb = x + (size_t)bb * NPTS * CDIM;
    float s = 0.0f;
#pragma unroll
    for (int k = 0; k < KNN; k++) s += xb[sidx[k] * CDIM + threadIdx.x];
    // pre-round to tf32: gemm1 A-staging becomes a pure copy (cvt idempotent)
    g_avg[(size_t)row * KPAD + threadIdx.x] =
        __uint_as_float(f2tf32(s * (1.0f / (float)KNN)));

    if (threadIdx.x < 16) {
        int c = threadIdx.x;
        float v = 0.0f;
        if (c < PDIM) {
            const float* pb = pos + bb * NPTS * PDIM;
#pragma unroll
            for (int k = 0; k < KNN; k++) v += pb[sidx[k] * PDIM + c];
            v *= (1.0f / (float)KNN);
        }
        g_avg[(size_t)row * KPAD + CDIM + c] = __uint_as_float(f2tf32(v));
    }
}

// ---------------- 2-term TF32 tensor-core GEMM --------------------------------
// C[M x 256] = op(A)[M x K] * B[K x 256]; C ~= Ah*Bh + Ah*Bl (rel err ~3.6e-4).
// B arrives PRE-SPLIT (Bh/Bl global arrays, computed once in prep) -> B staging
// is a pure copy. A: FUSE=false -> pre-rounded tf32 (copy); FUSE=true ->
// BN+ReLU then cvt online. BM=128, BN=128, BK=16, 8 warps (2m x 4n),
// single-buffered smem (136 stride, conflict-free), register prefetch.
__device__ __forceinline__ void mma_tf32(float* c, uint32_t a0, uint32_t a1,
                                         uint32_t a2, uint32_t a3,
                                         uint32_t b0, uint32_t b1) {
    asm volatile(
        "mma.sync.aligned.m16n8k8.row.col.f32.tf32.tf32.f32 "
        "{%0,%1,%2,%3}, {%4,%5,%6,%7}, {%8,%9}, {%0,%1,%2,%3};\n"
        : "+f"(c[0]), "+f"(c[1]), "+f"(c[2]), "+f"(c[3])
        : "r"(a0), "r"(a1), "r"(a2), "r"(a3), "r"(b0), "r"(b1));
}

template <bool FUSE, int LAYER>
__global__ void __launch_bounds__(256, 2) gemm_tc(const float* __restrict__ A, int lda, int K,
                                                  const float* __restrict__ Bhg,
                                                  const float* __restrict__ Blg,
                                                  float* __restrict__ C) {
    __shared__ float Ah[16][136];                  // A stage transposed [k][m], tf32 hi
    __shared__ float Bh[16][136], Bl[16][136];     // B stage [k][n], hi/lo
    __shared__ float s_sc[ODIM], s_sh[ODIM];
    __shared__ float sS[2][128], sQ[2][128];

    int tid = threadIdx.x;
    if (FUSE) { s_sc[tid] = g_scale[0][tid]; s_sh[tid] = g_shift[0][tid]; }

    int wid = tid >> 5;
    int lane = tid & 31;
    int gid = lane >> 2;            // group id 0..7
    int tig = lane & 3;             // thread-in-group 0..3
    int wm = wid >> 2;              // 0..1 -> 64-row half
    int wn = wid & 3;               // 0..3 -> 32-col slice
    int mBase = blockIdx.y * 128;
    int nBase = blockIdx.x * 128;

    int ar0 = tid >> 2;             // A rows 0..63 (+64)
    int akq = (tid & 3) << 2;       // A k-offset
    int bkr = tid >> 5;             // B k-rows 0..7 (+8)
    int bcq = (tid & 31) << 2;      // B n-offset

    const float* Ab  = A   + (size_t)mBase * lda;
    const float* Bbh = Bhg + nBase;
    const float* Bbl = Blg + nBase;

    if (FUSE) __syncthreads();

    float acc[4][4][4];
#pragma unroll
    for (int mt = 0; mt < 4; mt++)
#pragma unroll
        for (int nt = 0; nt < 4; nt++)
#pragma unroll
            for (int e = 0; e < 4; e++) acc[mt][nt][e] = 0.0f;

    // prologue: tile 0
    float4 ra0 = *(const float4*)(Ab + (size_t)ar0 * lda + akq);
    float4 ra1 = *(const float4*)(Ab + (size_t)(ar0 + 64) * lda + akq);
    float4 rbh0 = *(const float4*)(Bbh + (size_t)bkr * ODIM + bcq);
    float4 rbh1 = *(const float4*)(Bbh + (size_t)(bkr + 8) * ODIM + bcq);
    float4 rbl0 = *(const float4*)(Bbl + (size_t)bkr * ODIM + bcq);
    float4 rbl1 = *(const float4*)(Bbl + (size_t)(bkr + 8) * ODIM + bcq);

    for (int k0 = 0; k0 < K; k0 += 16) {
        // ---- stage: A (copy or BN+ReLU+cvt), B pure copy ----
        float av0[4] = {ra0.x, ra0.y, ra0.z, ra0.w};
        float av1[4] = {ra1.x, ra1.y, ra1.z, ra1.w};
        if (FUSE) {
#pragma unroll
            for (int i = 0; i < 4; i++) {
                float sc = s_sc[k0 + akq + i], sh = s_sh[k0 + akq + i];
                av0[i] = __uint_as_float(f2tf32(fmaxf(fmaf(av0[i], sc, sh), 0.0f)));
                av1[i] = __uint_as_float(f2tf32(fmaxf(fmaf(av1[i], sc, sh), 0.0f)));
            }
        }
#pragma unroll
        for (int i = 0; i < 4; i++) {
            Ah[akq + i][ar0]      = av0[i];
            Ah[akq + i][ar0 + 64] = av1[i];
        }
        *(float4*)&Bh[bkr][bcq] = rbh0;  *(float4*)&Bh[bkr + 8][bcq] = rbh1;
        *(float4*)&Bl[bkr][bcq] = rbl0;  *(float4*)&Bl[bkr + 8][bcq] = rbl1;
        __syncthreads();

        if (k0 + 16 < K) {          // prefetch next tile under the MMA block
            ra0 = *(const float4*)(Ab + (size_t)ar0 * lda + k0 + 16 + akq);
            ra1 = *(const float4*)(Ab + (size_t)(ar0 + 64) * lda + k0 + 16 + akq);
            rbh0 = *(const float4*)(Bbh + (size_t)(k0 + 16 + bkr) * ODIM + bcq);
            rbh1 = *(const float4*)(Bbh + (size_t)(k0 + 24 + bkr) * ODIM + bcq);
            rbl0 = *(const float4*)(Bbl + (size_t)(k0 + 16 + bkr) * ODIM + bcq);
            rbl1 = *(const float4*)(Bbl + (size_t)(k0 + 24 + bkr) * ODIM + bcq);
        }

        // ---- compute: 2 k8 steps, 2 Dekker terms ----
#pragma unroll
        for (int g = 0; g < 2; g++) {
            int kr0 = g * 8 + tig;
            int kr1 = kr0 + 4;
            uint32_t bh[4][2], bl[4][2];
#pragma unroll
            for (int nt = 0; nt < 4; nt++) {
                int nn = wn * 32 + nt * 8 + gid;
                bh[nt][0] = __float_as_uint(Bh[kr0][nn]);
                bh[nt][1] = __float_as_uint(Bh[kr1][nn]);
                bl[nt][0] = __float_as_uint(Bl[kr0][nn]);
                bl[nt][1] = __float_as_uint(Bl[kr1][nn]);
            }
#pragma unroll
            for (int mt = 0; mt < 4; mt++) {
                int m = wm * 64 + mt * 16 + gid;
                uint32_t ah0 = __float_as_uint(Ah[kr0][m]);
                uint32_t ah1 = __float_as_uint(Ah[kr0][m + 8]);
                uint32_t ah2 = __float_as_uint(Ah[kr1][m]);
                uint32_t ah3 = __float_as_uint(Ah[kr1][m + 8]);
#pragma unroll
                for (int nt = 0; nt < 4; nt++) {
                    mma_tf32(acc[mt][nt], ah0, ah1, ah2, ah3, bh[nt][0], bh[nt][1]);
                    mma_tf32(acc[mt][nt], ah0, ah1, ah2, ah3, bl[nt][0], bl[nt][1]);
                }
            }
        }
        __syncthreads();
    }

    // ---- write C ----
#pragma unroll
    for (int mt = 0; mt < 4; mt++) {
#pragma unroll
        for (int nt = 0; nt < 4; nt++) {
            int r = mBase + wm * 64 + mt * 16 + gid;
            int cc = nBase + wn * 32 + nt * 8 + 2 * tig;
            *(float2*)(C + (size_t)r * ODIM + cc) = make_float2(acc[mt][nt][0], acc[mt][nt][1]);
            *(float2*)(C + (size_t)(r + 8) * ODIM + cc) = make_float2(acc[mt][nt][2], acc[mt][nt][3]);
        }
    }

    // ---- epilogue: deterministic per-channel partial sum / sumsq ----
    float cs[4][2], cq[4][2];
#pragma unroll
    for (int nt = 0; nt < 4; nt++) {
#pragma unroll
        for (int e = 0; e < 2; e++) {
            float s = 0.0f, q = 0.0f;
#pragma unroll
            for (int mt = 0; mt < 4; mt++) {
                float v0 = acc[mt][nt][e], v1 = acc[mt][nt][e + 2];
                s += v0 + v1;
                q = fmaf(v0, v0, q);
                q = fmaf(v1, v1, q);
            }
            cs[nt][e] = s; cq[nt][e] = q;
        }
    }
#pragma unroll
    for (int nt = 0; nt < 4; nt++) {
#pragma unroll
        for (int e = 0; e < 2; e++) {
            float s = cs[nt][e], q = cq[nt][e];
            s += __shfl_xor_sync(0xFFFFFFFFu, s, 4);
            s += __shfl_xor_sync(0xFFFFFFFFu, s, 8);
            s += __shfl_xor_sync(0xFFFFFFFFu, s, 16);
            q += __shfl_xor_sync(0xFFFFFFFFu, q, 4);
            q += __shfl_xor_sync(0xFFFFFFFFu, q, 8);
            q += __shfl_xor_sync(0xFFFFFFFFu, q, 16);
            if (gid == 0) {
                int c = wn * 32 + nt * 8 + 2 * tig + e;
                sS[wm][c] = s;  sQ[wm][c] = q;
            }
        }
    }
    __syncthreads();
    if (tid < 128) {
        float s = sS[0][tid] + sS[1][tid];
        float q = sQ[0][tid] + sQ[1][tid];
        g_partM[LAYER][blockIdx.y][nBase + tid] = s;
        g_partM[LAYER][blockIdx.y][ODIM + nBase + tid] = q;
    }
}

// reduce per-mblock partials + compute per-channel scale/shift
__global__ void __launch_bounds__(512) stats_reduce_kernel(int layer,
                                                           const float* __restrict__ gamma,
                                                           const float* __restrict__ beta) {
    __shared__ float ssum[2 * ODIM];
    int t = threadIdx.x;
    float s = 0.0f;
    for (int r = 0; r < MBLK; r++) s += g_partM[layer][r][t];
    ssum[t] = s;
    __syncthreads();
    if (t < ODIM) {
        float mu  = ssum[t] * INVN;
        float var = fmaf(-mu, mu, ssum[ODIM + t] * INVN);
        float sc = gamma[t] * rsqrtf(var + BN_EPS);
        g_scale[layer][t] = sc;
        g_shift[layer][t] = fmaf(-mu, sc, beta[t]);
    }
}

// ---------------- BN apply (final layer, no ReLU), float4 elementwise ---------
__global__ void __launch_bounds__(256) bn_apply_kernel(float* __restrict__ Y, int layer) {
    int idx = blockIdx.x * blockDim.x + threadIdx.x;
    int e = idx * 4;
    int c = e & (ODIM - 1);
    float4 v = *(const float4*)(Y + e);
    float o[4] = {v.x, v.y, v.z, v.w};
#pragma unroll
    for (int j = 0; j < 4; j++) {
        int ch = c + j;
        o[j] = fmaf(o[j], g_scale[layer][ch], g_shift[layer][ch]);
    }
    *(float4*)(Y + e) = make_float4(o[0], o[1], o[2], o[3]);
}

// ---------------- launcher ----------------------------------------------------
extern "C" void kernel_launch(void* const* d_in, const int* in_sizes, int n_in,
                              void* d_out, int out_size) {
    const float* x   = (const float*)d_in[0];   // [8,2048,128]
    const float* pos = (const float*)d_in[1];   // [8,2048,3]
    const float* W1  = (const float*)d_in[2];   // [131,256]
    // d_in[3] = b1 (cancels under train-mode BN)
    const float* g1  = (const float*)d_in[4];
    const float* be1 = (const float*)d_in[5];
    const float* W2  = (const float*)d_in[6];   // [256,256]
    // d_in[7] = b2 (cancels)
    const float* g2  = (const float*)d_in[8];
    const float* be2 = (const float*)d_in[9];
    float* out = (float*)d_out;                 // [8,2048,256]

    prep1_kernel<<<KPAD, ODIM>>>(W1);
    prep2_kernel<<<ODIM, ODIM>>>(W2);
    knn_kernel<<<BATCH * (NPTS / 32), 64>>>(pos);
    gather_avg_kernel<<<ROWS, 128>>>(x, pos);

    float *avg = nullptr, *w1h = nullptr, *w1l = nullptr;
    float *w2h = nullptr, *w2l = nullptr, *c1 = nullptr;
    cudaGetSymbolAddress((void**)&avg, g_avg);
    cudaGetSymbolAddress((void**)&w1h, g_w1h);
    cudaGetSymbolAddress((void**)&w1l, g_w1l);
    cudaGetSymbolAddress((void**)&w2h, g_w2h);
    cudaGetSymbolAddress((void**)&w2l, g_w2l);
    cudaGetSymbolAddress((void**)&c1,  g_c1);

    dim3 ggrid(ODIM / 128, ROWS / 128);         // (2, 128)
    gemm_tc<false, 0><<<ggrid, 256>>>(avg, KPAD, KPAD, w1h, w1l, c1);
    stats_reduce_kernel<<<1, 512>>>(0, g1, be1);

    // layer-2 GEMM with BN1+ReLU fused into A staging; stats fused in epilogue
    gemm_tc<true, 1><<<ggrid, 256>>>(c1, ODIM, ODIM, w2h, w2l, out);
    stats_reduce_kernel<<<1, 512>>>(1, g2, be2);
    bn_apply_kernel<<<ROWS * ODIM / 4 / 256, 256>>>(out, 1);
}

// round 15
// speedup vs baseline: 1.0772x; 1.0772x over previous
#include <cuda_runtime.h>
#include <cuda_bf16.h>
#include <math.h>
#include <stdint.h>

// Problem constants
#define BATCH 8
#define NPTS  2048
#define CDIM  128
#define PDIM  3
#define ODIM  256
#define KNN   16
#define ROWS  (BATCH * NPTS)       // 16384
#define KPAD  144                  // 131 padded up to multiple of 16
#define BN_EPS 1e-5f
#define INVN  (1.0f / (float)ROWS)
#define MBLK  (ROWS / 128)         // 128 m-blocks in gemm grid

typedef unsigned long long u64;

// ---------------- scratch (static device memory; no allocations) -------------
__device__ int   g_nn[ROWS * KNN];                 // 1 MB
__device__ float g_avg[ROWS * KPAD];               // 9.4 MB
__device__ float g_w1p[KPAD * ODIM];               // 147 KB (padded W1)
__device__ float g_c1[ROWS * ODIM];                // 16.8 MB (pre-BN layer1)
__device__ float g_partM[2][MBLK][2 * ODIM];       // gemm-epilogue partial sum|sumsq
__device__ float g_scale[2][ODIM];                 // BN scale per layer
__device__ float g_shift[2][ODIM];                 // BN shift per layer

// ---------------- prep: pad W1 (R13 version) ----------------------------------
__global__ void prep_kernel(const float* __restrict__ W1) {
    int k = blockIdx.x;          // 0..143
    int o = threadIdx.x;         // 0..255
    g_w1p[k * ODIM + o] = (k < 131) ? W1[k * ODIM + o] : 0.0f;
}

// ---------------- KNN (R13 measured-best version, verbatim) -------------------
// 2 threads per query (even/odd point parity); register top-16 via deferred
// batched inserts; unique u64 keys (dist_bits<<32 | idx) = exact top_k
// semantics; REDUX warp-max; direct seeding from first 16 candidates.
__device__ __forceinline__ u64 umax64(u64 a, u64 b) { return a > b ? a : b; }

__device__ __forceinline__ u64 max16(const u64 (&bk)[KNN]) {
    u64 m0 = umax64(bk[0], bk[1]),   m1 = umax64(bk[2], bk[3]);
    u64 m2 = umax64(bk[4], bk[5]),   m3 = umax64(bk[6], bk[7]);
    u64 m4 = umax64(bk[8], bk[9]),   m5 = umax64(bk[10], bk[11]);
    u64 m6 = umax64(bk[12], bk[13]), m7 = umax64(bk[14], bk[15]);
    m0 = umax64(m0, m1); m2 = umax64(m2, m3);
    m4 = umax64(m4, m5); m6 = umax64(m6, m7);
    m0 = umax64(m0, m2); m4 = umax64(m4, m6);
    return umax64(m0, m4);
}

__device__ __forceinline__ void insert16(u64 (&bk)[KNN], u64& wmax, u64 key) {
#pragma unroll
    for (int k = 0; k < KNN; k++) {
        if (bk[k] == wmax) bk[k] = key;      // unique keys: exactly one slot
    }
    wmax = max16(bk);
}

__global__ void __launch_bounds__(64) knn_kernel(const float* __restrict__ pos) {
    __shared__ float4 sp[NPTS];                    // 32 KB
    __shared__ u64 sbuf[16][64];                   // 8 KB, [slot][lane]
    int tid = threadIdx.x;
    int bb = blockIdx.x >> 6;                      // batch (64 blocks per batch)
    int r0 = (blockIdx.x & 63) << 5;               // query offset (32 queries/block)
    const float* pb = pos + bb * NPTS * PDIM;
    for (int j = tid; j < NPTS; j += 64) {
        sp[j] = make_float4(pb[j * 3 + 0], pb[j * 3 + 1], pb[j * 3 + 2], 0.0f);
    }
    __syncthreads();

    int qi = r0 + (tid >> 1);                      // query index (pairs share)
    int sub = tid & 1;                             // parity of points scanned
    float4 q = sp[qi];

    // seed: thread's first 16 candidates (points 0..31) are the initial top-16
    u64 bk[KNN];
#pragma unroll
    for (int k = 0; k < KNN; k++) {
        int j = 2 * k + sub;
        float4 p = sp[j];
        float dx = q.x - p.x, dy = q.y - p.y, dz = q.z - p.z;
        float d = dx * dx + dy * dy + dz * dz;
        bk[k] = ((u64)__float_as_uint(d) << 32) | (unsigned)j;
    }
    u64 wmax = max16(bk);

    int n = 0;
    for (int j0 = 32; j0 < NPTS; j0 += 16) {
#pragma unroll
        for (int c = 0; c < 8; c++) {
            int j = j0 + 2 * c + sub;
            float4 p = sp[j];
            float dx = q.x - p.x, dy = q.y - p.y, dz = q.z - p.z;
            float d = dx * dx + dy * dy + dz * dz;
            u64 key = ((u64)__float_as_uint(d) << 32) | (unsigned)j;
            if (key < wmax) { sbuf[n][tid] = key; n++; }   // predicated push
        }
        if (__any_sync(0xFFFFFFFFu, n >= 8)) {
            int mx = __reduce_max_sync(0xFFFFFFFFu, n);    // REDUX, 1 instr
            for (int k = 0; k < mx; k++) {          // lockstep insert rounds
                u64 key = sbuf[k][tid];
                if (k < n && key < wmax) insert16(bk, wmax, key);
            }
            n = 0;
        }
    }
    {   // final flush
        int mx = __reduce_max_sync(0xFFFFFFFFu, n);
        for (int k = 0; k < mx; k++) {
            u64 key = sbuf[k][tid];
            if (k < n && key < wmax) insert16(bk, wmax, key);
        }
    }

    // pair merge: even lane absorbs odd lane's 16 keys (union superset, exact)
#pragma unroll
    for (int k = 0; k < KNN; k++) {
        u64 pk = __shfl_xor_sync(0xFFFFFFFFu, bk[k], 1);
        if (sub == 0 && pk < wmax) insert16(bk, wmax, pk);
    }
    if (sub == 0) {
        int* o = g_nn + (bb * NPTS + qi) * KNN;
#pragma unroll
        for (int k = 0; k < KNN; k++) o[k] = (int)(bk[k] & 0xFFFFFFFFu);
    }
}

// ---------------- gather neighbors + mean: float4 vectorized ------------------
// THIS ROUND'S ONE CHANGE. 4 rows/block, 1 warp per row: 32 threads x 4
// channels, 16 LDG.128 each (was 16 LDG.32 per thread). Per-channel sum
// order unchanged (k = 0..15 then x 1/16) -> bit-identical avg.
__global__ void __launch_bounds__(128) gather_avg_kernel(const float* __restrict__ x,
                                                         const float* __restrict__ pos) {
    int rowBase = blockIdx.x * 4;
    __shared__ int sidx[4][KNN];
    if (threadIdx.x < 64)
        ((int*)sidx)[threadIdx.x] = g_nn[rowBase * KNN + threadIdx.x];
    __syncthreads();

    int r = threadIdx.x >> 5;              // warp -> row
    int c4 = (threadIdx.x & 31) << 2;      // 4 channels per thread
    int row = rowBase + r;
    int bb = row >> 11;
    const float* xb = x + (size_t)bb * NPTS * CDIM;

    float4 s = make_float4(0.0f, 0.0f, 0.0f, 0.0f);
#pragma unroll
    for (int k = 0; k < KNN; k++) {
        float4 v = *(const float4*)(xb + (size_t)sidx[r][k] * CDIM + c4);
        s.x += v.x; s.y += v.y; s.z += v.z; s.w += v.w;
    }
    const float inv = 1.0f / (float)KNN;
    s.x *= inv; s.y *= inv; s.z *= inv; s.w *= inv;
    *(float4*)(g_avg + (size_t)row * KPAD + c4) = s;

    if (threadIdx.x < 64) {                // pad columns 128..143 (pos-mean / 0)
        int rr = threadIdx.x >> 4;
        int c = threadIdx.x & 15;
        int row2 = rowBase + rr;
        int bb2 = row2 >> 11;
        float v = 0.0f;
        if (c < PDIM) {
            const float* pb = pos + bb2 * NPTS * PDIM;
#pragma unroll
            for (int k = 0; k < KNN; k++) v += pb[sidx[rr][k] * PDIM + c];
            v *= inv;
        }
        g_avg[(size_t)row2 * KPAD + CDIM + c] = v;
    }
}

// ---------------- 2-term TF32 tensor-core GEMM (R13 measured-best, verbatim) --
// C[M x 256] = op(A)[M x K] * B[K x 256]; C ~= Ah*Bh + Ah*Bl (rel err ~3.6e-4).
// BM=128, BN=128, BK=16, 8 warps (2m x 4n), warp tile 64x32, single-buffered
// smem (136 row stride, conflict-free) with register prefetch.
__device__ __forceinline__ uint32_t f2tf32(float x) {
    uint32_t r;
    asm("cvt.rna.tf32.f32 %0, %1;" : "=r"(r) : "f"(x));
    return r;
}
__device__ __forceinline__ void tf32_split(float x, float& hi, float& lo) {
    uint32_t h = f2tf32(x);
    hi = __uint_as_float(h);
    lo = __uint_as_float(f2tf32(x - hi));
}
__device__ __forceinline__ void mma_tf32(float* c, uint32_t a0, uint32_t a1,
                                         uint32_t a2, uint32_t a3,
                                         uint32_t b0, uint32_t b1) {
    asm volatile(
        "mma.sync.aligned.m16n8k8.row.col.f32.tf32.tf32.f32 "
        "{%0,%1,%2,%3}, {%4,%5,%6,%7}, {%8,%9}, {%0,%1,%2,%3};\n"
        : "+f"(c[0]), "+f"(c[1]), "+f"(c[2]), "+f"(c[3])
        : "r"(a0), "r"(a1), "r"(a2), "r"(a3), "r"(b0), "r"(b1));
}

template <bool FUSE, int LAYER>
__global__ void __launch_bounds__(256, 2) gemm_tc(const float* __restrict__ A, int lda, int K,
                                                  const float* __restrict__ B,
                                                  float* __restrict__ C) {
    __shared__ float Ah[16][136];                  // A stage transposed [k][m], tf32 hi
    __shared__ float Bh[16][136], Bl[16][136];     // B stage [k][n], hi/lo
    __shared__ float s_sc[ODIM], s_sh[ODIM];
    __shared__ float sS[2][128], sQ[2][128];

    int tid = threadIdx.x;
    if (FUSE) { s_sc[tid] = g_scale[0][tid]; s_sh[tid] = g_shift[0][tid]; }

    int wid = tid >> 5;
    int lane = tid & 31;
    int gid = lane >> 2;            // group id 0..7
    int tig = lane & 3;             // thread-in-group 0..3
    int wm = wid >> 2;              // 0..1 -> 64-row half
    int wn = wid & 3;               // 0..3 -> 32-col slice
    int mBase = blockIdx.y * 128;
    int nBase = blockIdx.x * 128;

    int ar0 = tid >> 2;             // A rows 0..63 (+64)
    int akq = (tid & 3) << 2;       // A k-offset
    int bkr = tid >> 5;             // B k-rows 0..7 (+8)
    int bcq = (tid & 31) << 2;      // B n-offset

    const float* Ab = A + (size_t)mBase * lda;
    const float* Bb = B + nBase;

    if (FUSE) __syncthreads();

    float acc[4][4][4];
#pragma unroll
    for (int mt = 0; mt < 4; mt++)
#pragma unroll
        for (int nt = 0; nt < 4; nt++)
#pragma unroll
            for (int e = 0; e < 4; e++) acc[mt][nt][e] = 0.0f;

    // prologue: tile 0
    float4 ra0 = *(const float4*)(Ab + (size_t)ar0 * lda + akq);
    float4 ra1 = *(const float4*)(Ab + (size_t)(ar0 + 64) * lda + akq);
    float4 rb0 = *(const float4*)(Bb + (size_t)bkr * ODIM + bcq);
    float4 rb1 = *(const float4*)(Bb + (size_t)(bkr + 8) * ODIM + bcq);

    for (int k0 = 0; k0 < K; k0 += 16) {
        // ---- stage (FUSE: BN+ReLU on A first); A hi-only, B hi/lo ----
        float av0[4] = {ra0.x, ra0.y, ra0.z, ra0.w};
        float av1[4] = {ra1.x, ra1.y, ra1.z, ra1.w};
        if (FUSE) {
#pragma unroll
            for (int i = 0; i < 4; i++) {
                float sc = s_sc[k0 + akq + i], sh = s_sh[k0 + akq + i];
                av0[i] = fmaxf(fmaf(av0[i], sc, sh), 0.0f);
                av1[i] = fmaxf(fmaf(av1[i], sc, sh), 0.0f);
            }
        }
#pragma unroll
        for (int i = 0; i < 4; i++) {
            Ah[akq + i][ar0]      = __uint_as_float(f2tf32(av0[i]));
            Ah[akq + i][ar0 + 64] = __uint_as_float(f2tf32(av1[i]));
        }
        {
            float4 h0, l0, h1, l1;
            tf32_split(rb0.x, h0.x, l0.x); tf32_split(rb0.y, h0.y, l0.y);
            tf32_split(rb0.z, h0.z, l0.z); tf32_split(rb0.w, h0.w, l0.w);
            tf32_split(rb1.x, h1.x, l1.x); tf32_split(rb1.y, h1.y, l1.y);
            tf32_split(rb1.z, h1.z, l1.z); tf32_split(rb1.w, h1.w, l1.w);
            *(float4*)&Bh[bkr][bcq] = h0;  *(float4*)&Bl[bkr][bcq] = l0;
            *(float4*)&Bh[bkr + 8][bcq] = h1;  *(float4*)&Bl[bkr + 8][bcq] = l1;
        }
        __syncthreads();

        if (k0 + 16 < K) {          // prefetch next tile under the MMA block
            ra0 = *(const float4*)(Ab + (size_t)ar0 * lda + k0 + 16 + akq);
            ra1 = *(const float4*)(Ab + (size_t)(ar0 + 64) * lda + k0 + 16 + akq);
            rb0 = *(const float4*)(Bb + (size_t)(k0 + 16 + bkr) * ODIM + bcq);
            rb1 = *(const float4*)(Bb + (size_t)(k0 + 24 + bkr) * ODIM + bcq);
        }

        // ---- compute: 2 k8 steps, 2 Dekker terms ----
#pragma unroll
        for (int g = 0; g < 2; g++) {
            int kr0 = g * 8 + tig;
            int kr1 = kr0 + 4;
            uint32_t bh[4][2], bl[4][2];
#pragma unroll
            for (int nt = 0; nt < 4; nt++) {
                int nn = wn * 32 + nt * 8 + gid;
                bh[nt][0] = __float_as_uint(Bh[kr0][nn]);
                bh[nt][1] = __float_as_uint(Bh[kr1][nn]);
                bl[nt][0] = __float_as_uint(Bl[kr0][nn]);
                bl[nt][1] = __float_as_uint(Bl[kr1][nn]);
            }
#pragma unroll
            for (int mt = 0; mt < 4; mt++) {
                int m = wm * 64 + mt * 16 + gid;
                uint32_t ah0 = __float_as_uint(Ah[kr0][m]);
                uint32_t ah1 = __float_as_uint(Ah[kr0][m + 8]);
                uint32_t ah2 = __float_as_uint(Ah[kr1][m]);
                uint32_t ah3 = __float_as_uint(Ah[kr1][m + 8]);
#pragma unroll
                for (int nt = 0; nt < 4; nt++) {
                    mma_tf32(acc[mt][nt], ah0, ah1, ah2, ah3, bh[nt][0], bh[nt][1]);
                    mma_tf32(acc[mt][nt], ah0, ah1, ah2, ah3, bl[nt][0], bl[nt][1]);
                }
            }
        }
        __syncthreads();
    }

    // ---- write C ----
#pragma unroll
    for (int mt = 0; mt < 4; mt++) {
#pragma unroll
        for (int nt = 0; nt < 4; nt++) {
            int r = mBase + wm * 64 + mt * 16 + gid;
            int cc = nBase + wn * 32 + nt * 8 + 2 * tig;
            *(float2*)(C + (size_t)r * ODIM + cc) = make_float2(acc[mt][nt][0], acc[mt][nt][1]);
            *(float2*)(C + (size_t)(r + 8) * ODIM + cc) = make_float2(acc[mt][nt][2], acc[mt][nt][3]);
        }
    }

    // ---- epilogue: deterministic per-channel partial sum / sumsq ----
    float cs[4][2], cq[4][2];
#pragma unroll
    for (int nt = 0; nt < 4; nt++) {
#pragma unroll
        for (int e = 0; e < 2; e++) {
            float s = 0.0f, q = 0.0f;
#pragma unroll
            for (int mt = 0; mt < 4; mt++) {
                float v0 = acc[mt][nt][e], v1 = acc[mt][nt][e + 2];
                s += v0 + v1;
                q = fmaf(v0, v0, q);
                q = fmaf(v1, v1, q);
            }
            cs[nt][e] = s; cq[nt][e] = q;
        }
    }
#pragma unroll
    for (int nt = 0; nt < 4; nt++) {
#pragma unroll
        for (int e = 0; e < 2; e++) {
            float s = cs[nt][e], q = cq[nt][e];
            s += __shfl_xor_sync(0xFFFFFFFFu, s, 4);
            s += __shfl_xor_sync(0xFFFFFFFFu, s, 8);
            s += __shfl_xor_sync(0xFFFFFFFFu, s, 16);
            q += __shfl_xor_sync(0xFFFFFFFFu, q, 4);
            q += __shfl_xor_sync(0xFFFFFFFFu, q, 8);
            q += __shfl_xor_sync(0xFFFFFFFFu, q, 16);
            if (gid == 0) {
                int c = wn * 32 + nt * 8 + 2 * tig + e;
                sS[wm][c] = s;  sQ[wm][c] = q;
            }
        }
    }
    __syncthreads();
    if (tid < 128) {
        float s = sS[0][tid] + sS[1][tid];
        float q = sQ[0][tid] + sQ[1][tid];
        g_partM[LAYER][blockIdx.y][nBase + tid] = s;
        g_partM[LAYER][blockIdx.y][ODIM + nBase + tid] = q;
    }
}

// reduce per-mblock partials + compute per-channel scale/shift
__global__ void __launch_bounds__(512) stats_reduce_kernel(int layer,
                                                           const float* __restrict__ gamma,
                                                           const float* __restrict__ beta) {
    __shared__ float ssum[2 * ODIM];
    int t = threadIdx.x;
    float s = 0.0f;
    for (int r = 0; r < MBLK; r++) s += g_partM[layer][r][t];
    ssum[t] = s;
    __syncthreads();
    if (t < ODIM) {
        float mu  = ssum[t] * INVN;
        float var = fmaf(-mu, mu, ssum[ODIM + t] * INVN);
        float sc = gamma[t] * rsqrtf(var + BN_EPS);
        g_scale[layer][t] = sc;
        g_shift[layer][t] = fmaf(-mu, sc, beta[t]);
    }
}

// ---------------- BN apply (final layer, no ReLU), float4 elementwise ---------
__global__ void __launch_bounds__(256) bn_apply_kernel(float* __restrict__ Y, int layer) {
    int idx = blockIdx.x * blockDim.x + threadIdx.x;
    int e = idx * 4;
    int c = e & (ODIM - 1);
    float4 v = *(const float4*)(Y + e);
    float o[4] = {v.x, v.y, v.z, v.w};
#pragma unroll
    for (int j = 0; j < 4; j++) {
        int ch = c + j;
        o[j] = fmaf(o[j], g_scale[layer][ch], g_shift[layer][ch]);
    }
    *(float4*)(Y + e) = make_float4(o[0], o[1], o[2], o[3]);
}

// ---------------- launcher ----------------------------------------------------
extern "C" void kernel_launch(void* const* d_in, const int* in_sizes, int n_in,
                              void* d_out, int out_size) {
    const float* x   = (const float*)d_in[0];   // [8,2048,128]
    const float* pos = (const float*)d_in[1];   // [8,2048,3]
    const float* W1  = (const float*)d_in[2];   // [131,256]
    // d_in[3] = b1 (cancels under train-mode BN)
    const float* g1  = (const float*)d_in[4];
    const float* be1 = (const float*)d_in[5];
    const float* W2  = (const float*)d_in[6];   // [256,256]
    // d_in[7] = b2 (cancels)
    const float* g2  = (const float*)d_in[8];
    const float* be2 = (const float*)d_in[9];
    float* out = (float*)d_out;                 // [8,2048,256]

    prep_kernel<<<KPAD, ODIM>>>(W1);
    knn_kernel<<<BATCH * (NPTS / 32), 64>>>(pos);
    gather_avg_kernel<<<ROWS / 4, 128>>>(x, pos);

    float* avg = nullptr; float* w1p = nullptr; float* c1 = nullptr;
    cudaGetSymbolAddress((void**)&avg, g_avg);
    cudaGetSymbolAddress((void**)&w1p, g_w1p);
    cudaGetSymbolAddress((void**)&c1,  g_c1);

    dim3 ggrid(ODIM / 128, ROWS / 128);         // (2, 128)
    gemm_tc<false, 0><<<ggrid, 256>>>(avg, KPAD, KPAD, w1p, c1);
    stats_reduce_kernel<<<1, 512>>>(0, g1, be1);

    // layer-2 GEMM with BN1+ReLU fused into A staging; stats fused in epilogue
    gemm_tc<true, 1><<<ggrid, 256>>>(c1, ODIM, ODIM, W2, out);
    stats_reduce_kernel<<<1, 512>>>(1, g2, be2);
    bn_apply_kernel<<<ROWS * ODIM / 4 / 256, 256>>>(out, 1);
}

// round 16
// speedup vs baseline: 1.0774x; 1.0002x over previous
#include <cuda_runtime.h>
#include <cuda_bf16.h>
#include <math.h>
#include <stdint.h>

// Problem constants
#define BATCH 8
#define NPTS  2048
#define CDIM  128
#define PDIM  3
#define ODIM  256
#define KNN   16
#define ROWS  (BATCH * NPTS)       // 16384
#define KPAD  144                  // 131 padded up to multiple of 16
#define BN_EPS 1e-5f
#define INVN  (1.0f / (float)ROWS)
#define MBLK  (ROWS / 128)         // 128 m-blocks in gemm grid

typedef unsigned long long u64;

// ---------------- scratch (static device memory; no allocations) -------------
__device__ int   g_nn[ROWS * KNN];                 // 1 MB
__device__ float g_avg[ROWS * KPAD];               // 9.4 MB
__device__ float g_w1p[KPAD * ODIM];               // 147 KB (padded W1)
__device__ float g_c1[ROWS * ODIM];                // 16.8 MB (pre-BN layer1)
__device__ float g_partM[2][MBLK][2 * ODIM];       // gemm-epilogue partial sum|sumsq
__device__ float g_scale[2][ODIM];                 // BN scale per layer
__device__ float g_shift[2][ODIM];                 // BN shift per layer

// ---------------- prep: pad W1 ------------------------------------------------
__global__ void prep_kernel(const float* __restrict__ W1) {
    int k = blockIdx.x;          // 0..143
    int o = threadIdx.x;         // 0..255
    g_w1p[k * ODIM + o] = (k < 131) ? W1[k * ODIM + o] : 0.0f;
}

// ---------------- KNN --------------------------------------------------------
// 2 threads per query (even/odd point parity); register top-16 via deferred
// batched inserts; unique u64 keys (dist_bits<<32 | idx) = exact top_k
// semantics. THIS ROUND'S ONE CHANGE: hot-loop gate is the FLOAT compare
// d <= wf (strict superset of key < wmax since wf = wmax's distance bits);
// the u64 key is built only on the rare push path, and flush/merge re-gate
// with the exact u64 compare -> final selected set is bit-identical.
__device__ __forceinline__ u64 umax64(u64 a, u64 b) { return a > b ? a : b; }

__device__ __forceinline__ u64 max16(const u64 (&bk)[KNN]) {
    u64 m0 = umax64(bk[0], bk[1]),   m1 = umax64(bk[2], bk[3]);
    u64 m2 = umax64(bk[4], bk[5]),   m3 = umax64(bk[6], bk[7]);
    u64 m4 = umax64(bk[8], bk[9]),   m5 = umax64(bk[10], bk[11]);
    u64 m6 = umax64(bk[12], bk[13]), m7 = umax64(bk[14], bk[15]);
    m0 = umax64(m0, m1); m2 = umax64(m2, m3);
    m4 = umax64(m4, m5); m6 = umax64(m6, m7);
    m0 = umax64(m0, m2); m4 = umax64(m4, m6);
    return umax64(m0, m4);
}

__device__ __forceinline__ void insert16(u64 (&bk)[KNN], u64& wmax, u64 key) {
#pragma unroll
    for (int k = 0; k < KNN; k++) {
        if (bk[k] == wmax) bk[k] = key;      // unique keys: exactly one slot
    }
    wmax = max16(bk);
}

__global__ void __launch_bounds__(64) knn_kernel(const float* __restrict__ pos) {
    __shared__ float4 sp[NPTS];                    // 32 KB
    __shared__ u64 sbuf[16][64];                   // 8 KB, [slot][lane]
    int tid = threadIdx.x;
    int bb = blockIdx.x >> 6;                      // batch (64 blocks per batch)
    int r0 = (blockIdx.x & 63) << 5;               // query offset (32 queries/block)
    const float* pb = pos + bb * NPTS * PDIM;
    for (int j = tid; j < NPTS; j += 64) {
        sp[j] = make_float4(pb[j * 3 + 0], pb[j * 3 + 1], pb[j * 3 + 2], 0.0f);
    }
    __syncthreads();

    int qi = r0 + (tid >> 1);                      // query index (pairs share)
    int sub = tid & 1;                             // parity of points scanned
    float4 q = sp[qi];

    // seed: thread's first 16 candidates (points 0..31) are the initial top-16
    u64 bk[KNN];
#pragma unroll
    for (int k = 0; k < KNN; k++) {
        int j = 2 * k + sub;
        float4 p = sp[j];
        float dx = q.x - p.x, dy = q.y - p.y, dz = q.z - p.z;
        float d = dx * dx + dy * dy + dz * dz;
        bk[k] = ((u64)__float_as_uint(d) << 32) | (unsigned)j;
    }
    u64 wmax = max16(bk);
    float wf = __uint_as_float((unsigned)(wmax >> 32));

    int n = 0;
    for (int j0 = 32; j0 < NPTS; j0 += 16) {
#pragma unroll
        for (int c = 0; c < 8; c++) {
            int j = j0 + 2 * c + sub;
            float4 p = sp[j];
            float dx = q.x - p.x, dy = q.y - p.y, dz = q.z - p.z;
            float d = dx * dx + dy * dy + dz * dz;
            if (d <= wf) {                          // float gate (superset)
                sbuf[n][tid] = ((u64)__float_as_uint(d) << 32) | (unsigned)j;
                n++;
            }
        }
        if (__any_sync(0xFFFFFFFFu, n >= 8)) {
            int mx = __reduce_max_sync(0xFFFFFFFFu, n);    // REDUX, 1 instr
            for (int k = 0; k < mx; k++) {          // lockstep insert rounds
                u64 key = sbuf[k][tid];
                if (k < n && key < wmax) insert16(bk, wmax, key);  // exact gate
            }
            n = 0;
            wf = __uint_as_float((unsigned)(wmax >> 32));
        }
    }
    {   // final flush
        int mx = __reduce_max_sync(0xFFFFFFFFu, n);
        for (int k = 0; k < mx; k++) {
            u64 key = sbuf[k][tid];
            if (k < n && key < wmax) insert16(bk, wmax, key);
        }
    }

    // pair merge: even lane absorbs odd lane's 16 keys (union superset, exact)
#pragma unroll
    for (int k = 0; k < KNN; k++) {
        u64 pk = __shfl_xor_sync(0xFFFFFFFFu, bk[k], 1);
        if (sub == 0 && pk < wmax) insert16(bk, wmax, pk);
    }
    if (sub == 0) {
        int* o = g_nn + (bb * NPTS + qi) * KNN;
#pragma unroll
        for (int k = 0; k < KNN; k++) o[k] = (int)(bk[k] & 0xFFFFFFFFu);
    }
}

// ---------------- gather neighbors + mean: float4 vectorized (R15 best) -------
__global__ void __launch_bounds__(128) gather_avg_kernel(const float* __restrict__ x,
                                                         const float* __restrict__ pos) {
    int rowBase = blockIdx.x * 4;
    __shared__ int sidx[4][KNN];
    if (threadIdx.x < 64)
        ((int*)sidx)[threadIdx.x] = g_nn[rowBase * KNN + threadIdx.x];
    __syncthreads();

    int r = threadIdx.x >> 5;              // warp -> row
    int c4 = (threadIdx.x & 31) << 2;      // 4 channels per thread
    int row = rowBase + r;
    int bb = row >> 11;
    const float* xb = x + (size_t)bb * NPTS * CDIM;

    float4 s = make_float4(0.0f, 0.0f, 0.0f, 0.0f);
#pragma unroll
    for (int k = 0; k < KNN; k++) {
        float4 v = *(const float4*)(xb + (size_t)sidx[r][k] * CDIM + c4);
        s.x += v.x; s.y += v.y; s.z += v.z; s.w += v.w;
    }
    const float inv = 1.0f / (float)KNN;
    s.x *= inv; s.y *= inv; s.z *= inv; s.w *= inv;
    *(float4*)(g_avg + (size_t)row * KPAD + c4) = s;

    if (threadIdx.x < 64) {                // pad columns 128..143 (pos-mean / 0)
        int rr = threadIdx.x >> 4;
        int c = threadIdx.x & 15;
        int row2 = rowBase + rr;
        int bb2 = row2 >> 11;
        float v = 0.0f;
        if (c < PDIM) {
            const float* pb = pos + bb2 * NPTS * PDIM;
#pragma unroll
            for (int k = 0; k < KNN; k++) v += pb[sidx[rr][k] * PDIM + c];
            v *= inv;
        }
        g_avg[(size_t)row2 * KPAD + CDIM + c] = v;
    }
}

// ---------------- 2-term TF32 tensor-core GEMM (measured-best, verbatim) ------
// C[M x 256] = op(A)[M x K] * B[K x 256]; C ~= Ah*Bh + Ah*Bl (rel err ~3.6e-4).
// BM=128, BN=128, BK=16, 8 warps (2m x 4n), warp tile 64x32, single-buffered
// smem (136 row stride, conflict-free) with register prefetch.
__device__ __forceinline__ uint32_t f2tf32(float x) {
    uint32_t r;
    asm("cvt.rna.tf32.f32 %0, %1;" : "=r"(r) : "f"(x));
    return r;
}
__device__ __forceinline__ void tf32_split(float x, float& hi, float& lo) {
    uint32_t h = f2tf32(x);
    hi = __uint_as_float(h);
    lo = __uint_as_float(f2tf32(x - hi));
}
__device__ __forceinline__ void mma_tf32(float* c, uint32_t a0, uint32_t a1,
                                         uint32_t a2, uint32_t a3,
                                         uint32_t b0, uint32_t b1) {
    asm volatile(
        "mma.sync.aligned.m16n8k8.row.col.f32.tf32.tf32.f32 "
        "{%0,%1,%2,%3}, {%4,%5,%6,%7}, {%8,%9}, {%0,%1,%2,%3};\n"
        : "+f"(c[0]), "+f"(c[1]), "+f"(c[2]), "+f"(c[3])
        : "r"(a0), "r"(a1), "r"(a2), "r"(a3), "r"(b0), "r"(b1));
}

template <bool FUSE, int LAYER>
__global__ void __launch_bounds__(256, 2) gemm_tc(const float* __restrict__ A, int lda, int K,
                                                  const float* __restrict__ B,
                                                  float* __restrict__ C) {
    __shared__ float Ah[16][136];                  // A stage transposed [k][m], tf32 hi
    __shared__ float Bh[16][136], Bl[16][136];     // B stage [k][n], hi/lo
    __shared__ float s_sc[ODIM], s_sh[ODIM];
    __shared__ float sS[2][128], sQ[2][128];

    int tid = threadIdx.x;
    if (FUSE) { s_sc[tid] = g_scale[0][tid]; s_sh[tid] = g_shift[0][tid]; }

    int wid = tid >> 5;
    int lane = tid & 31;
    int gid = lane >> 2;            // group id 0..7
    int tig = lane & 3;             // thread-in-group 0..3
    int wm = wid >> 2;              // 0..1 -> 64-row half
    int wn = wid & 3;               // 0..3 -> 32-col slice
    int mBase = blockIdx.y * 128;
    int nBase = blockIdx.x * 128;

    int ar0 = tid >> 2;             // A rows 0..63 (+64)
    int akq = (tid & 3) << 2;       // A k-offset
    int bkr = tid >> 5;             // B k-rows 0..7 (+8)
    int bcq = (tid & 31) << 2;      // B n-offset

    const float* Ab = A + (size_t)mBase * lda;
    const float* Bb = B + nBase;

    if (FUSE) __syncthreads();

    float acc[4][4][4];
#pragma unroll
    for (int mt = 0; mt < 4; mt++)
#pragma unroll
        for (int nt = 0; nt < 4; nt++)
#pragma unroll
            for (int e = 0; e < 4; e++) acc[mt][nt][e] = 0.0f;

    // prologue: tile 0
    float4 ra0 = *(const float4*)(Ab + (size_t)ar0 * lda + akq);
    float4 ra1 = *(const float4*)(Ab + (size_t)(ar0 + 64) * lda + akq);
    float4 rb0 = *(const float4*)(Bb + (size_t)bkr * ODIM + bcq);
    float4 rb1 = *(const float4*)(Bb + (size_t)(bkr + 8) * ODIM + bcq);

    for (int k0 = 0; k0 < K; k0 += 16) {
        // ---- stage (FUSE: BN+ReLU on A first); A hi-only, B hi/lo ----
        float av0[4] = {ra0.x, ra0.y, ra0.z, ra0.w};
        float av1[4] = {ra1.x, ra1.y, ra1.z, ra1.w};
        if (FUSE) {
#pragma unroll
            for (int i = 0; i < 4; i++) {
                float sc = s_sc[k0 + akq + i], sh = s_sh[k0 + akq + i];
                av0[i] = fmaxf(fmaf(av0[i], sc, sh), 0.0f);
                av1[i] = fmaxf(fmaf(av1[i], sc, sh), 0.0f);
            }
        }
#pragma unroll
        for (int i = 0; i < 4; i++) {
            Ah[akq + i][ar0]      = __uint_as_float(f2tf32(av0[i]));
            Ah[akq + i][ar0 + 64] = __uint_as_float(f2tf32(av1[i]));
        }
        {
            float4 h0, l0, h1, l1;
            tf32_split(rb0.x, h0.x, l0.x); tf32_split(rb0.y, h0.y, l0.y);
            tf32_split(rb0.z, h0.z, l0.z); tf32_split(rb0.w, h0.w, l0.w);
            tf32_split(rb1.x, h1.x, l1.x); tf32_split(rb1.y, h1.y, l1.y);
            tf32_split(rb1.z, h1.z, l1.z); tf32_split(rb1.w, h1.w, l1.w);
            *(float4*)&Bh[bkr][bcq] = h0;  *(float4*)&Bl[bkr][bcq] = l0;
            *(float4*)&Bh[bkr + 8][bcq] = h1;  *(float4*)&Bl[bkr + 8][bcq] = l1;
        }
        __syncthreads();

        if (k0 + 16 < K) {          // prefetch next tile under the MMA block
            ra0 = *(const float4*)(Ab + (size_t)ar0 * lda + k0 + 16 + akq);
            ra1 = *(const float4*)(Ab + (size_t)(ar0 + 64) * lda + k0 + 16 + akq);
            rb0 = *(const float4*)(Bb + (size_t)(k0 + 16 + bkr) * ODIM + bcq);
            rb1 = *(const float4*)(Bb + (size_t)(k0 + 24 + bkr) * ODIM + bcq);
        }

        // ---- compute: 2 k8 steps, 2 Dekker terms ----
#pragma unroll
        for (int g = 0; g < 2; g++) {
            int kr0 = g * 8 + tig;
            int kr1 = kr0 + 4;
            uint32_t bh[4][2], bl[4][2];
#pragma unroll
            for (int nt = 0; nt < 4; nt++) {
                int nn = wn * 32 + nt * 8 + gid;
                bh[nt][0] = __float_as_uint(Bh[kr0][nn]);
                bh[nt][1] = __float_as_uint(Bh[kr1][nn]);
                bl[nt][0] = __float_as_uint(Bl[kr0][nn]);
                bl[nt][1] = __float_as_uint(Bl[kr1][nn]);
            }
#pragma unroll
            for (int mt = 0; mt < 4; mt++) {
                int m = wm * 64 + mt * 16 + gid;
                uint32_t ah0 = __float_as_uint(Ah[kr0][m]);
                uint32_t ah1 = __float_as_uint(Ah[kr0][m + 8]);
                uint32_t ah2 = __float_as_uint(Ah[kr1][m]);
                uint32_t ah3 = __float_as_uint(Ah[kr1][m + 8]);
#pragma unroll
                for (int nt = 0; nt < 4; nt++) {
                    mma_tf32(acc[mt][nt], ah0, ah1, ah2, ah3, bh[nt][0], bh[nt][1]);
                    mma_tf32(acc[mt][nt], ah0, ah1, ah2, ah3, bl[nt][0], bl[nt][1]);
                }
            }
        }
        __syncthreads();
    }

    // ---- write C ----
#pragma unroll
    for (int mt = 0; mt < 4; mt++) {
#pragma unroll
        for (int nt = 0; nt < 4; nt++) {
            int r = mBase + wm * 64 + mt * 16 + gid;
            int cc = nBase + wn * 32 + nt * 8 + 2 * tig;
            *(float2*)(C + (size_t)r * ODIM + cc) = make_float2(acc[mt][nt][0], acc[mt][nt][1]);
            *(float2*)(C + (size_t)(r + 8) * ODIM + cc) = make_float2(acc[mt][nt][2], acc[mt][nt][3]);
        }
    }

    // ---- epilogue: deterministic per-channel partial sum / sumsq ----
    float cs[4][2], cq[4][2];
#pragma unroll
    for (int nt = 0; nt < 4; nt++) {
#pragma unroll
        for (int e = 0; e < 2; e++) {
            float s = 0.0f, q = 0.0f;
#pragma unroll
            for (int mt = 0; mt < 4; mt++) {
                float v0 = acc[mt][nt][e], v1 = acc[mt][nt][e + 2];
                s += v0 + v1;
                q = fmaf(v0, v0, q);
                q = fmaf(v1, v1, q);
            }
            cs[nt][e] = s; cq[nt][e] = q;
        }
    }
#pragma unroll
    for (int nt = 0; nt < 4; nt++) {
#pragma unroll
        for (int e = 0; e < 2; e++) {
            float s = cs[nt][e], q = cq[nt][e];
            s += __shfl_xor_sync(0xFFFFFFFFu, s, 4);
            s += __shfl_xor_sync(0xFFFFFFFFu, s, 8);
            s += __shfl_xor_sync(0xFFFFFFFFu, s, 16);
            q += __shfl_xor_sync(0xFFFFFFFFu, q, 4);
            q += __shfl_xor_sync(0xFFFFFFFFu, q, 8);
            q += __shfl_xor_sync(0xFFFFFFFFu, q, 16);
            if (gid == 0) {
                int c = wn * 32 + nt * 8 + 2 * tig + e;
                sS[wm][c] = s;  sQ[wm][c] = q;
            }
        }
    }
    __syncthreads();
    if (tid < 128) {
        float s = sS[0][tid] + sS[1][tid];
        float q = sQ[0][tid] + sQ[1][tid];
        g_partM[LAYER][blockIdx.y][nBase + tid] = s;
        g_partM[LAYER][blockIdx.y][ODIM + nBase + tid] = q;
    }
}

// reduce per-mblock partials + compute per-channel scale/shift
__global__ void __launch_bounds__(512) stats_reduce_kernel(int layer,
                                                           const float* __restrict__ gamma,
                                                           const float* __restrict__ beta) {
    __shared__ float ssum[2 * ODIM];
    int t = threadIdx.x;
    float s = 0.0f;
    for (int r = 0; r < MBLK; r++) s += g_partM[layer][r][t];
    ssum[t] = s;
    __syncthreads();
    if (t < ODIM) {
        float mu  = ssum[t] * INVN;
        float var = fmaf(-mu, mu, ssum[ODIM + t] * INVN);
        float sc = gamma[t] * rsqrtf(var + BN_EPS);
        g_scale[layer][t] = sc;
        g_shift[layer][t] = fmaf(-mu, sc, beta[t]);
    }
}

// ---------------- BN apply (final layer, no ReLU), float4 elementwise ---------
__global__ void __launch_bounds__(256) bn_apply_kernel(float* __restrict__ Y, int layer) {
    int idx = blockIdx.x * blockDim.x + threadIdx.x;
    int e = idx * 4;
    int c = e & (ODIM - 1);
    float4 v = *(const float4*)(Y + e);
    float o[4] = {v.x, v.y, v.z, v.w};
#pragma unroll
    for (int j = 0; j < 4; j++) {
        int ch = c + j;
        o[j] = fmaf(o[j], g_scale[layer][ch], g_shift[layer][ch]);
    }
    *(float4*)(Y + e) = make_float4(o[0], o[1], o[2], o[3]);
}

// ---------------- launcher ----------------------------------------------------
extern "C" void kernel_launch(void* const* d_in, const int* in_sizes, int n_in,
                              void* d_out, int out_size) {
    const float* x   = (const float*)d_in[0];   // [8,2048,128]
    const float* pos = (const float*)d_in[1];   // [8,2048,3]
    const float* W1  = (const float*)d_in[2];   // [131,256]
    // d_in[3] = b1 (cancels under train-mode BN)
    const float* g1  = (const float*)d_in[4];
    const float* be1 = (const float*)d_in[5];
    const float* W2  = (const float*)d_in[6];   // [256,256]
    // d_in[7] = b2 (cancels)
    const float* g2  = (const float*)d_in[8];
    const float* be2 = (const float*)d_in[9];
    float* out = (float*)d_out;                 // [8,2048,256]

    prep_kernel<<<KPAD, ODIM>>>(W1);
    knn_kernel<<<BATCH * (NPTS / 32), 64>>>(pos);
    gather_avg_kernel<<<ROWS / 4, 128>>>(x, pos);

    float* avg = nullptr; float* w1p = nullptr; float* c1 = nullptr;
    cudaGetSymbolAddress((void**)&avg, g_avg);
    cudaGetSymbolAddress((void**)&w1p, g_w1p);
    cudaGetSymbolAddress((void**)&c1,  g_c1);

    dim3 ggrid(ODIM / 128, ROWS / 128);         // (2, 128)
    gemm_tc<false, 0><<<ggrid, 256>>>(avg, KPAD, KPAD, w1p, c1);
    stats_reduce_kernel<<<1, 512>>>(0, g1, be1);

    // layer-2 GEMM with BN1+ReLU fused into A staging; stats fused in epilogue
    gemm_tc<true, 1><<<ggrid, 256>>>(c1, ODIM, ODIM, W2, out);
    stats_reduce_kernel<<<1, 512>>>(1, g2, be2);
    bn_apply_kernel<<<ROWS * ODIM / 4 / 256, 256>>>(out, 1);
}

// round 17
// speedup vs baseline: 1.1001x; 1.0211x over previous
#include <cuda_runtime.h>
#include <cuda_bf16.h>
#include <math.h>
#include <stdint.h>

// Problem constants
#define BATCH 8
#define NPTS  2048
#define CDIM  128
#define PDIM  3
#define ODIM  256
#define KNN   16
#define ROWS  (BATCH * NPTS)       // 16384
#define KPAD  144                  // 131 padded up to multiple of 16
#define BN_EPS 1e-5f
#define INVN  (1.0f / (float)ROWS)
#define MBLK  (ROWS / 128)         // 128 m-blocks in gemm grid

typedef unsigned long long u64;

// ---------------- scratch (static device memory; no allocations) -------------
__device__ int   g_nn[ROWS * KNN];                 // 1 MB
__device__ float g_avg[ROWS * KPAD];               // 9.4 MB
__device__ float g_w1p[KPAD * ODIM];               // 147 KB (padded W1)
__device__ float g_c1[ROWS * ODIM];                // 16.8 MB (pre-BN layer1)
__device__ float g_partM[2][MBLK][2 * ODIM];       // gemm-epilogue partial sum|sumsq
__device__ float g_scale[2][ODIM];                 // BN scale per layer
__device__ float g_shift[2][ODIM];                 // BN shift per layer

// ---------------- prep: pad W1 ------------------------------------------------
__global__ void prep_kernel(const float* __restrict__ W1) {
    int k = blockIdx.x;          // 0..143
    int o = threadIdx.x;         // 0..255
    g_w1p[k * ODIM + o] = (k < 131) ? W1[k * ODIM + o] : 0.0f;
}

// ---------------- KNN (measured-best: R13 + float gate) ------------------------
__device__ __forceinline__ u64 umax64(u64 a, u64 b) { return a > b ? a : b; }

__device__ __forceinline__ u64 max16(const u64 (&bk)[KNN]) {
    u64 m0 = umax64(bk[0], bk[1]),   m1 = umax64(bk[2], bk[3]);
    u64 m2 = umax64(bk[4], bk[5]),   m3 = umax64(bk[6], bk[7]);
    u64 m4 = umax64(bk[8], bk[9]),   m5 = umax64(bk[10], bk[11]);
    u64 m6 = umax64(bk[12], bk[13]), m7 = umax64(bk[14], bk[15]);
    m0 = umax64(m0, m1); m2 = umax64(m2, m3);
    m4 = umax64(m4, m5); m6 = umax64(m6, m7);
    m0 = umax64(m0, m2); m4 = umax64(m4, m6);
    return umax64(m0, m4);
}

__device__ __forceinline__ void insert16(u64 (&bk)[KNN], u64& wmax, u64 key) {
#pragma unroll
    for (int k = 0; k < KNN; k++) {
        if (bk[k] == wmax) bk[k] = key;      // unique keys: exactly one slot
    }
    wmax = max16(bk);
}

__global__ void __launch_bounds__(64) knn_kernel(const float* __restrict__ pos) {
    __shared__ float4 sp[NPTS];                    // 32 KB
    __shared__ u64 sbuf[16][64];                   // 8 KB, [slot][lane]
    int tid = threadIdx.x;
    int bb = blockIdx.x >> 6;                      // batch (64 blocks per batch)
    int r0 = (blockIdx.x & 63) << 5;               // query offset (32 queries/block)
    const float* pb = pos + bb * NPTS * PDIM;
    for (int j = tid; j < NPTS; j += 64) {
        sp[j] = make_float4(pb[j * 3 + 0], pb[j * 3 + 1], pb[j * 3 + 2], 0.0f);
    }
    __syncthreads();

    int qi = r0 + (tid >> 1);                      // query index (pairs share)
    int sub = tid & 1;                             // parity of points scanned
    float4 q = sp[qi];

    // seed: thread's first 16 candidates (points 0..31) are the initial top-16
    u64 bk[KNN];
#pragma unroll
    for (int k = 0; k < KNN; k++) {
        int j = 2 * k + sub;
        float4 p = sp[j];
        float dx = q.x - p.x, dy = q.y - p.y, dz = q.z - p.z;
        float d = dx * dx + dy * dy + dz * dz;
        bk[k] = ((u64)__float_as_uint(d) << 32) | (unsigned)j;
    }
    u64 wmax = max16(bk);
    float wf = __uint_as_float((unsigned)(wmax >> 32));

    int n = 0;
    for (int j0 = 32; j0 < NPTS; j0 += 16) {
#pragma unroll
        for (int c = 0; c < 8; c++) {
            int j = j0 + 2 * c + sub;
            float4 p = sp[j];
            float dx = q.x - p.x, dy = q.y - p.y, dz = q.z - p.z;
            float d = dx * dx + dy * dy + dz * dz;
            if (d <= wf) {                          // float gate (superset)
                sbuf[n][tid] = ((u64)__float_as_uint(d) << 32) | (unsigned)j;
                n++;
            }
        }
        if (__any_sync(0xFFFFFFFFu, n >= 8)) {
            int mx = __reduce_max_sync(0xFFFFFFFFu, n);    // REDUX, 1 instr
            for (int k = 0; k < mx; k++) {          // lockstep insert rounds
                u64 key = sbuf[k][tid];
                if (k < n && key < wmax) insert16(bk, wmax, key);  // exact gate
            }
            n = 0;
            wf = __uint_as_float((unsigned)(wmax >> 32));
        }
    }
    {   // final flush
        int mx = __reduce_max_sync(0xFFFFFFFFu, n);
        for (int k = 0; k < mx; k++) {
            u64 key = sbuf[k][tid];
            if (k < n && key < wmax) insert16(bk, wmax, key);
        }
    }

    // pair merge: even lane absorbs odd lane's 16 keys (union superset, exact)
#pragma unroll
    for (int k = 0; k < KNN; k++) {
        u64 pk = __shfl_xor_sync(0xFFFFFFFFu, bk[k], 1);
        if (sub == 0 && pk < wmax) insert16(bk, wmax, pk);
    }
    if (sub == 0) {
        int* o = g_nn + (bb * NPTS + qi) * KNN;
#pragma unroll
        for (int k = 0; k < KNN; k++) o[k] = (int)(bk[k] & 0xFFFFFFFFu);
    }
}

// ---------------- gather neighbors + mean: float4 vectorized (R15 best) -------
__global__ void __launch_bounds__(128) gather_avg_kernel(const float* __restrict__ x,
                                                         const float* __restrict__ pos) {
    int rowBase = blockIdx.x * 4;
    __shared__ int sidx[4][KNN];
    if (threadIdx.x < 64)
        ((int*)sidx)[threadIdx.x] = g_nn[rowBase * KNN + threadIdx.x];
    __syncthreads();

    int r = threadIdx.x >> 5;              // warp -> row
    int c4 = (threadIdx.x & 31) << 2;      // 4 channels per thread
    int row = rowBase + r;
    int bb = row >> 11;
    const float* xb = x + (size_t)bb * NPTS * CDIM;

    float4 s = make_float4(0.0f, 0.0f, 0.0f, 0.0f);
#pragma unroll
    for (int k = 0; k < KNN; k++) {
        float4 v = *(const float4*)(xb + (size_t)sidx[r][k] * CDIM + c4);
        s.x += v.x; s.y += v.y; s.z += v.z; s.w += v.w;
    }
    const float inv = 1.0f / (float)KNN;
    s.x *= inv; s.y *= inv; s.z *= inv; s.w *= inv;
    *(float4*)(g_avg + (size_t)row * KPAD + c4) = s;

    if (threadIdx.x < 64) {                // pad columns 128..143 (pos-mean / 0)
        int rr = threadIdx.x >> 4;
        int c = threadIdx.x & 15;
        int row2 = rowBase + rr;
        int bb2 = row2 >> 11;
        float v = 0.0f;
        if (c < PDIM) {
            const float* pb = pos + bb2 * NPTS * PDIM;
#pragma unroll
            for (int k = 0; k < KNN; k++) v += pb[sidx[rr][k] * PDIM + c];
            v *= inv;
        }
        g_avg[(size_t)row2 * KPAD + CDIM + c] = v;
    }
}

// ---------------- 2-term TF32 tensor-core GEMM (measured-best, verbatim) ------
__device__ __forceinline__ uint32_t f2tf32(float x) {
    uint32_t r;
    asm("cvt.rna.tf32.f32 %0, %1;" : "=r"(r) : "f"(x));
    return r;
}
__device__ __forceinline__ void tf32_split(float x, float& hi, float& lo) {
    uint32_t h = f2tf32(x);
    hi = __uint_as_float(h);
    lo = __uint_as_float(f2tf32(x - hi));
}
__device__ __forceinline__ void mma_tf32(float* c, uint32_t a0, uint32_t a1,
                                         uint32_t a2, uint32_t a3,
                                         uint32_t b0, uint32_t b1) {
    asm volatile(
        "mma.sync.aligned.m16n8k8.row.col.f32.tf32.tf32.f32 "
        "{%0,%1,%2,%3}, {%4,%5,%6,%7}, {%8,%9}, {%0,%1,%2,%3};\n"
        : "+f"(c[0]), "+f"(c[1]), "+f"(c[2]), "+f"(c[3])
        : "r"(a0), "r"(a1), "r"(a2), "r"(a3), "r"(b0), "r"(b1));
}

template <bool FUSE, int LAYER>
__global__ void __launch_bounds__(256, 2) gemm_tc(const float* __restrict__ A, int lda, int K,
                                                  const float* __restrict__ B,
                                                  float* __restrict__ C) {
    __shared__ float Ah[16][136];                  // A stage transposed [k][m], tf32 hi
    __shared__ float Bh[16][136], Bl[16][136];     // B stage [k][n], hi/lo
    __shared__ float s_sc[ODIM], s_sh[ODIM];
    __shared__ float sS[2][128], sQ[2][128];

    int tid = threadIdx.x;
    if (FUSE) { s_sc[tid] = g_scale[0][tid]; s_sh[tid] = g_shift[0][tid]; }

    int wid = tid >> 5;
    int lane = tid & 31;
    int gid = lane >> 2;            // group id 0..7
    int tig = lane & 3;             // thread-in-group 0..3
    int wm = wid >> 2;              // 0..1 -> 64-row half
    int wn = wid & 3;               // 0..3 -> 32-col slice
    int mBase = blockIdx.y * 128;
    int nBase = blockIdx.x * 128;

    int ar0 = tid >> 2;             // A rows 0..63 (+64)
    int akq = (tid & 3) << 2;       // A k-offset
    int bkr = tid >> 5;             // B k-rows 0..7 (+8)
    int bcq = (tid & 31) << 2;      // B n-offset

    const float* Ab = A + (size_t)mBase * lda;
    const float* Bb = B + nBase;

    if (FUSE) __syncthreads();

    float acc[4][4][4];
#pragma unroll
    for (int mt = 0; mt < 4; mt++)
#pragma unroll
        for (int nt = 0; nt < 4; nt++)
#pragma unroll
            for (int e = 0; e < 4; e++) acc[mt][nt][e] = 0.0f;

    // prologue: tile 0
    float4 ra0 = *(const float4*)(Ab + (size_t)ar0 * lda + akq);
    float4 ra1 = *(const float4*)(Ab + (size_t)(ar0 + 64) * lda + akq);
    float4 rb0 = *(const float4*)(Bb + (size_t)bkr * ODIM + bcq);
    float4 rb1 = *(const float4*)(Bb + (size_t)(bkr + 8) * ODIM + bcq);

    for (int k0 = 0; k0 < K; k0 += 16) {
        // ---- stage (FUSE: BN+ReLU on A first); A hi-only, B hi/lo ----
        float av0[4] = {ra0.x, ra0.y, ra0.z, ra0.w};
        float av1[4] = {ra1.x, ra1.y, ra1.z, ra1.w};
        if (FUSE) {
#pragma unroll
            for (int i = 0; i < 4; i++) {
                float sc = s_sc[k0 + akq + i], sh = s_sh[k0 + akq + i];
                av0[i] = fmaxf(fmaf(av0[i], sc, sh), 0.0f);
                av1[i] = fmaxf(fmaf(av1[i], sc, sh), 0.0f);
            }
        }
#pragma unroll
        for (int i = 0; i < 4; i++) {
            Ah[akq + i][ar0]      = __uint_as_float(f2tf32(av0[i]));
            Ah[akq + i][ar0 + 64] = __uint_as_float(f2tf32(av1[i]));
        }
        {
            float4 h0, l0, h1, l1;
            tf32_split(rb0.x, h0.x, l0.x); tf32_split(rb0.y, h0.y, l0.y);
            tf32_split(rb0.z, h0.z, l0.z); tf32_split(rb0.w, h0.w, l0.w);
            tf32_split(rb1.x, h1.x, l1.x); tf32_split(rb1.y, h1.y, l1.y);
            tf32_split(rb1.z, h1.z, l1.z); tf32_split(rb1.w, h1.w, l1.w);
            *(float4*)&Bh[bkr][bcq] = h0;  *(float4*)&Bl[bkr][bcq] = l0;
            *(float4*)&Bh[bkr + 8][bcq] = h1;  *(float4*)&Bl[bkr + 8][bcq] = l1;
        }
        __syncthreads();

        if (k0 + 16 < K) {          // prefetch next tile under the MMA block
            ra0 = *(const float4*)(Ab + (size_t)ar0 * lda + k0 + 16 + akq);
            ra1 = *(const float4*)(Ab + (size_t)(ar0 + 64) * lda + k0 + 16 + akq);
            rb0 = *(const float4*)(Bb + (size_t)(k0 + 16 + bkr) * ODIM + bcq);
            rb1 = *(const float4*)(Bb + (size_t)(k0 + 24 + bkr) * ODIM + bcq);
        }

        // ---- compute: 2 k8 steps, 2 Dekker terms ----
#pragma unroll
        for (int g = 0; g < 2; g++) {
            int kr0 = g * 8 + tig;
            int kr1 = kr0 + 4;
            uint32_t bh[4][2], bl[4][2];
#pragma unroll
            for (int nt = 0; nt < 4; nt++) {
                int nn = wn * 32 + nt * 8 + gid;
                bh[nt][0] = __float_as_uint(Bh[kr0][nn]);
                bh[nt][1] = __float_as_uint(Bh[kr1][nn]);
                bl[nt][0] = __float_as_uint(Bl[kr0][nn]);
                bl[nt][1] = __float_as_uint(Bl[kr1][nn]);
            }
#pragma unroll
            for (int mt = 0; mt < 4; mt++) {
                int m = wm * 64 + mt * 16 + gid;
                uint32_t ah0 = __float_as_uint(Ah[kr0][m]);
                uint32_t ah1 = __float_as_uint(Ah[kr0][m + 8]);
                uint32_t ah2 = __float_as_uint(Ah[kr1][m]);
                uint32_t ah3 = __float_as_uint(Ah[kr1][m + 8]);
#pragma unroll
                for (int nt = 0; nt < 4; nt++) {
                    mma_tf32(acc[mt][nt], ah0, ah1, ah2, ah3, bh[nt][0], bh[nt][1]);
                    mma_tf32(acc[mt][nt], ah0, ah1, ah2, ah3, bl[nt][0], bl[nt][1]);
                }
            }
        }
        __syncthreads();
    }

    // ---- write C ----
#pragma unroll
    for (int mt = 0; mt < 4; mt++) {
#pragma unroll
        for (int nt = 0; nt < 4; nt++) {
            int r = mBase + wm * 64 + mt * 16 + gid;
            int cc = nBase + wn * 32 + nt * 8 + 2 * tig;
            *(float2*)(C + (size_t)r * ODIM + cc) = make_float2(acc[mt][nt][0], acc[mt][nt][1]);
            *(float2*)(C + (size_t)(r + 8) * ODIM + cc) = make_float2(acc[mt][nt][2], acc[mt][nt][3]);
        }
    }

    // ---- epilogue: deterministic per-channel partial sum / sumsq ----
    float cs[4][2], cq[4][2];
#pragma unroll
    for (int nt = 0; nt < 4; nt++) {
#pragma unroll
        for (int e = 0; e < 2; e++) {
            float s = 0.0f, q = 0.0f;
#pragma unroll
            for (int mt = 0; mt < 4; mt++) {
                float v0 = acc[mt][nt][e], v1 = acc[mt][nt][e + 2];
                s += v0 + v1;
                q = fmaf(v0, v0, q);
                q = fmaf(v1, v1, q);
            }
            cs[nt][e] = s; cq[nt][e] = q;
        }
    }
#pragma unroll
    for (int nt = 0; nt < 4; nt++) {
#pragma unroll
        for (int e = 0; e < 2; e++) {
            float s = cs[nt][e], q = cq[nt][e];
            s += __shfl_xor_sync(0xFFFFFFFFu, s, 4);
            s += __shfl_xor_sync(0xFFFFFFFFu, s, 8);
            s += __shfl_xor_sync(0xFFFFFFFFu, s, 16);
            q += __shfl_xor_sync(0xFFFFFFFFu, q, 4);
            q += __shfl_xor_sync(0xFFFFFFFFu, q, 8);
            q += __shfl_xor_sync(0xFFFFFFFFu, q, 16);
            if (gid == 0) {
                int c = wn * 32 + nt * 8 + 2 * tig + e;
                sS[wm][c] = s;  sQ[wm][c] = q;
            }
        }
    }
    __syncthreads();
    if (tid < 128) {
        float s = sS[0][tid] + sS[1][tid];
        float q = sQ[0][tid] + sQ[1][tid];
        g_partM[LAYER][blockIdx.y][nBase + tid] = s;
        g_partM[LAYER][blockIdx.y][ODIM + nBase + tid] = q;
    }
}

// ---------------- parallel stats reduce (THIS ROUND'S ONE CHANGE) --------------
// Was: 1 block x 512 threads, 128 sequential rounds through one SM's LSU
// (~15 us, on the critical path twice). Now: 8 blocks x 512 threads; block
// owns 32 channels; each thread sums 8 of 128 partials (sum AND sumsq), then
// fixed-order smem tree 16->8->4->2->1. Deterministic; summation order
// changes -> BN stats differ at ~1e-7 (rel_err pinned by 3.6e-4 tf32 term).
__global__ void __launch_bounds__(512) stats_reduce_kernel(int layer,
                                                           const float* __restrict__ gamma,
                                                           const float* __restrict__ beta) {
    __shared__ float rs[16][33], rq[16][33];
    int tt = threadIdx.x & 31;           // channel within block
    int rc = threadIdx.x >> 5;           // r-chunk 0..15
    int c = blockIdx.x * 32 + tt;        // global channel

    float s = 0.0f, q = 0.0f;
#pragma unroll
    for (int i = 0; i < 8; i++) {
        int r = rc * 8 + i;
        s += g_partM[layer][r][c];
        q += g_partM[layer][r][ODIM + c];
    }
    rs[rc][tt] = s;  rq[rc][tt] = q;
    __syncthreads();
    if (rc < 8) { rs[rc][tt] += rs[rc + 8][tt];  rq[rc][tt] += rq[rc + 8][tt]; }
    __syncthreads();
    if (rc < 4) { rs[rc][tt] += rs[rc + 4][tt];  rq[rc][tt] += rq[rc + 4][tt]; }
    __syncthreads();
    if (rc < 2) { rs[rc][tt] += rs[rc + 2][tt];  rq[rc][tt] += rq[rc + 2][tt]; }
    __syncthreads();
    if (rc == 0) {
        float ss = rs[0][tt] + rs[1][tt];
        float qq = rq[0][tt] + rq[1][tt];
        float mu  = ss * INVN;
        float var = fmaf(-mu, mu, qq * INVN);
        float sc = gamma[c] * rsqrtf(var + BN_EPS);
        g_scale[layer][c] = sc;
        g_shift[layer][c] = fmaf(-mu, sc, beta[c]);
    }
}

// ---------------- BN apply (final layer, no ReLU), float4 elementwise ---------
__global__ void __launch_bounds__(256) bn_apply_kernel(float* __restrict__ Y, int layer) {
    int idx = blockIdx.x * blockDim.x + threadIdx.x;
    int e = idx * 4;
    int c = e & (ODIM - 1);
    float4 v = *(const float4*)(Y + e);
    float o[4] = {v.x, v.y, v.z, v.w};
#pragma unroll
    for (int j = 0; j < 4; j++) {
        int ch = c + j;
        o[j] = fmaf(o[j], g_scale[layer][ch], g_shift[layer][ch]);
    }
    *(float4*)(Y + e) = make_float4(o[0], o[1], o[2], o[3]);
}

// ---------------- launcher ----------------------------------------------------
extern "C" void kernel_launch(void* const* d_in, const int* in_sizes, int n_in,
                              void* d_out, int out_size) {
    const float* x   = (const float*)d_in[0];   // [8,2048,128]
    const float* pos = (const float*)d_in[1];   // [8,2048,3]
    const float* W1  = (const float*)d_in[2];   // [131,256]
    // d_in[3] = b1 (cancels under train-mode BN)
    const float* g1  = (const float*)d_in[4];
    const float* be1 = (const float*)d_in[5];
    const float* W2  = (const float*)d_in[6];   // [256,256]
    // d_in[7] = b2 (cancels)
    const float* g2  = (const float*)d_in[8];
    const float* be2 = (const float*)d_in[9];
    float* out = (float*)d_out;                 // [8,2048,256]

    prep_kernel<<<KPAD, ODIM>>>(W1);
    knn_kernel<<<BATCH * (NPTS / 32), 64>>>(pos);
    gather_avg_kernel<<<ROWS / 4, 128>>>(x, pos);

    float* avg = nullptr; float* w1p = nullptr; float* c1 = nullptr;
    cudaGetSymbolAddress((void**)&avg, g_avg);
    cudaGetSymbolAddress((void**)&w1p, g_w1p);
    cudaGetSymbolAddress((void**)&c1,  g_c1);

    dim3 ggrid(ODIM / 128, ROWS / 128);         // (2, 128)
    gemm_tc<false, 0><<<ggrid, 256>>>(avg, KPAD, KPAD, w1p, c1);
    stats_reduce_kernel<<<ODIM / 32, 512>>>(0, g1, be1);

    // layer-2 GEMM with BN1+ReLU fused into A staging; stats fused in epilogue
    gemm_tc<true, 1><<<ggrid, 256>>>(c1, ODIM, ODIM, W2, out);
    stats_reduce_kernel<<<ODIM / 32, 512>>>(1, g2, be2);
    bn_apply_kernel<<<ROWS * ODIM / 4 / 256, 256>>>(out, 1);
}